// round 14
// baseline (speedup 1.0000x reference)
#include <cuda_runtime.h>
#include <math.h>

#define DD    64
#define HH    128
#define WW    128
#define HW    (HH * WW)            // 16384
#define BC    128
#define CCH   64
#define SLAB  ((size_t)DD * HW)    // 1,048,576 per (b,c)
#define NTHR  128                  // 4 warps; warp = 4 output rows x full W
#define NCHUNK 8                   // H split into 8 chunks of 16 rows
#define CH_ROWS 16
#define LROWS 18                   // 16 output rows + 2 halo rows
#define ROW_F4 (WW / 4)            // 32 float4 per row
#define PLANE_F4 (LROWS * ROW_F4)  // 576 float4 per tile-plane
#define RING  4                    // slot = z & 3; pairs (0,1)/(2,3) alternate
#define SMEM_BYTES (RING * PLANE_F4 * 16)  // 36864 B

typedef unsigned long long u64;

__device__ float g_psum[BC * NCHUNK];
__device__ float g_psq [BC * NCHUNK];
__device__ float g_mean[BC];
__device__ float g_rstd[BC];

// ---- packed fp32x2 helpers ----
__device__ __forceinline__ u64 pk2(float lo, float hi) {
    u64 r;
    asm("mov.b64 %0, {%1, %2};" : "=l"(r)
        : "r"(__float_as_uint(lo)), "r"(__float_as_uint(hi)));
    return r;
}
__device__ __forceinline__ void upk2(u64 v, float& lo, float& hi) {
    unsigned int a, b;
    asm("mov.b64 {%0, %1}, %2;" : "=r"(a), "=r"(b) : "l"(v));
    lo = __uint_as_float(a); hi = __uint_as_float(b);
}
__device__ __forceinline__ void fma2i(u64& acc, u64 a, u64 b) {
    asm("fma.rn.f32x2 %0, %1, %2, %0;" : "+l"(acc) : "l"(a), "l"(b));
}
__device__ __forceinline__ u64 fma2o(u64 a, u64 b, u64 c) {
    u64 d;
    asm("fma.rn.f32x2 %0, %1, %2, %3;" : "=l"(d) : "l"(a), "l"(b), "l"(c));
    return d;
}
__device__ __forceinline__ u64 mul2(u64 a, u64 b) {
    u64 d;
    asm("mul.rn.f32x2 %0, %1, %2;" : "=l"(d) : "l"(a), "l"(b));
    return d;
}
__device__ __forceinline__ void add2i(u64& acc, u64 a) {
    asm("add.rn.f32x2 %0, %1, %0;" : "+l"(acc) : "l"(a));
}
__device__ __forceinline__ void commit_g() {
    asm volatile("cp.async.commit_group;" ::: "memory");
}

// ---- async tile-plane load: 18 rows x 128 cols, zero-filled at H edges ----
__device__ __forceinline__ void load_plane(const float* __restrict__ xs, int z, int h0,
                                           float4* __restrict__ buf, int tid)
{
    const float* src = xs + (size_t)z * HW;
    unsigned int sbase = (unsigned int)__cvta_generic_to_shared(buf);
    #pragma unroll
    for (int it = 0; it < 5; ++it) {                 // 576 f4 / 128 thr = 4.5
        int i = tid + it * NTHR;
        if (it < 4 || i < PLANE_F4) {
            int row = i >> 5;
            int c4  = i & 31;
            int h   = h0 - 1 + row;
            if ((unsigned)h < (unsigned)HH) {
                const float* g = src + h * WW + c4 * 4;
                unsigned int sa = sbase + i * 16;
                asm volatile("cp.async.cg.shared.global [%0], [%1], 16;"
                             :: "r"(sa), "l"(g));
            } else {
                buf[i] = make_float4(0.f, 0.f, 0.f, 0.f);  // H zero-pad
            }
        }
    }
}

// ---- ONE sweep over the warp's 6 smem rows feeding up to THREE targets ----
// O += W(dz=2)*plane (completes out[z-1]); N += W(dz=1)*plane; F = W(dz=0)*plane.
// F is always "fresh": first tap per accumulator is mul (no zero-init needed).
// NFRESH: N is also fresh (only for the very first plane, z = 0).
template<bool HO, bool HF, bool NFRESH>
__device__ __forceinline__ void conv3(const float4* __restrict__ buf, int olb, int lane,
    const u64 (&W2p)[9], const u64 (&W1p)[9], const u64 (&W0p)[9],
    u64 (&O)[8], u64 (&N)[8], u64 (&F)[8])
{
    #pragma unroll
    for (int r = 0; r < 6; ++r) {
        float4 q = buf[(olb + r) * ROW_F4 + lane];
        float left  = __shfl_up_sync(0xffffffffu, q.w, 1);
        float right = __shfl_down_sync(0xffffffffu, q.x, 1);
        if (lane == 0)  left  = 0.f;   // true W zero-pad
        if (lane == 31) right = 0.f;
        u64 pp0 = pk2(left, q.x);
        u64 pp1 = pk2(q.x,  q.y);
        u64 pp2 = pk2(q.y,  q.z);
        u64 pp3 = pk2(q.z,  q.w);
        u64 pp4 = pk2(q.w,  right);
        #pragma unroll
        for (int oo = 0; oo < 4; ++oo) {
            const int dy = r - oo;                   // tap index; folds at compile time
            if (dy < 0 || dy > 2) continue;
            if (HO) {
                const u64 w0 = W2p[dy * 3 + 0], w1 = W2p[dy * 3 + 1], w2 = W2p[dy * 3 + 2];
                fma2i(O[2 * oo + 0], pp0, w0);
                fma2i(O[2 * oo + 0], pp1, w1);
                fma2i(O[2 * oo + 0], pp2, w2);
                fma2i(O[2 * oo + 1], pp2, w0);
                fma2i(O[2 * oo + 1], pp3, w1);
                fma2i(O[2 * oo + 1], pp4, w2);
            }
            {
                const u64 w0 = W1p[dy * 3 + 0], w1 = W1p[dy * 3 + 1], w2 = W1p[dy * 3 + 2];
                if (NFRESH && dy == 0) {             // first-ever touch of this output
                    N[2 * oo + 0] = mul2(pp0, w0);
                    N[2 * oo + 1] = mul2(pp2, w0);
                } else {
                    fma2i(N[2 * oo + 0], pp0, w0);
                    fma2i(N[2 * oo + 1], pp2, w0);
                }
                fma2i(N[2 * oo + 0], pp1, w1);
                fma2i(N[2 * oo + 0], pp2, w2);
                fma2i(N[2 * oo + 1], pp3, w1);
                fma2i(N[2 * oo + 1], pp4, w2);
            }
            if (HF) {
                const u64 w0 = W0p[dy * 3 + 0], w1 = W0p[dy * 3 + 1], w2 = W0p[dy * 3 + 2];
                if (dy == 0) {                       // F bank is fresh: overwrite, no init
                    F[2 * oo + 0] = mul2(pp0, w0);
                    F[2 * oo + 1] = mul2(pp2, w0);
                } else {
                    fma2i(F[2 * oo + 0], pp0, w0);
                    fma2i(F[2 * oo + 1], pp2, w0);
                }
                fma2i(F[2 * oo + 0], pp1, w1);
                fma2i(F[2 * oo + 0], pp2, w2);
                fma2i(F[2 * oo + 1], pp3, w1);
                fma2i(F[2 * oo + 1], pp4, w2);
            }
        }
    }
}

// ---- finalize a completed output plane: stats (pass1) or normalize+relu+store (pass2) ----
template<int PASS>
__device__ __forceinline__ void finalize(u64 (&A)[8], int d, u64& s2, u64& q2,
                                         u64 gsc2, u64 bsc2, float* __restrict__ outp)
{
    if (PASS == 1) {
        #pragma unroll
        for (int i = 0; i < 8; ++i) { add2i(s2, A[i]); fma2i(q2, A[i], A[i]); }
    } else {
        float* os = outp + (size_t)d * HW;
        #pragma unroll
        for (int oo = 0; oo < 4; ++oo) {
            u64 ya = fma2o(A[2 * oo + 0], gsc2, bsc2);
            u64 yb = fma2o(A[2 * oo + 1], gsc2, bsc2);
            float a0, a1, a2, a3;
            upk2(ya, a0, a1); upk2(yb, a2, a3);
            float4 r4;
            r4.x = fmaxf(a0, 0.f); r4.y = fmaxf(a1, 0.f);
            r4.z = fmaxf(a2, 0.f); r4.w = fmaxf(a3, 0.f);
            *(float4*)(os + oo * WW) = r4;
        }
    }
}

// ---- SUPERSTEP: consume planes z (slot SA) and z+1 (slot SB) behind ONE wait+barrier.
// Prefetch planes z+2, z+3 into the vacated slot pair (SA^2, SB^2), one commit group.
// Bank roles on entry: O = out[z-1] (w0,w1 done), N = out[z] (w0 done), F = free.
// Retires out[z-1] and out[z]; exit roles chain as (O,N,F) -> next call (F,O,N).
template<int PASS, int SA, int SB, bool FIRST, bool LAST>
__device__ __forceinline__ void sstep(int z, const float* __restrict__ xs,
        float4* __restrict__ smem4, int h0, int tid, int olb, int lane,
        const u64 (&W2p)[9], const u64 (&W1p)[9], const u64 (&W0p)[9],
        u64 (&O)[8], u64 (&N)[8], u64 (&F)[8],
        u64& s2, u64& q2, u64 gsc2, u64 bsc2, float* __restrict__ outp)
{
    asm volatile("cp.async.wait_group 0;" ::: "memory");  // planes z, z+1 resident
    __syncthreads();                                      // reads of vacated pair done
    if (!LAST) {
        load_plane(xs, z + 2, h0, smem4 + (SA ^ 2) * PLANE_F4, tid);
        load_plane(xs, z + 3, h0, smem4 + (SB ^ 2) * PLANE_F4, tid);
        commit_g();
    }
    // plane z
    conv3<!FIRST, true, FIRST>(smem4 + SA * PLANE_F4, olb, lane, W2p, W1p, W0p, O, N, F);
    if (!FIRST) finalize<PASS>(O, z - 1, s2, q2, gsc2, bsc2, outp);
    // plane z+1 (roles shift; retired O bank becomes the fresh F)
    conv3<true, !LAST, false>(smem4 + SB * PLANE_F4, olb, lane, W2p, W1p, W0p, N, F, O);
    finalize<PASS>(N, z, s2, q2, gsc2, bsc2, outp);
    if (LAST) finalize<PASS>(F, z + 1, s2, q2, gsc2, bsc2, outp);  // out[63]: W2 tap is zero
}

// PASS 1: streaming conv + per-CTA (sum,sumsq).  PASS 2: conv + norm + relu + store.
template<int PASS>
__global__ void __launch_bounds__(NTHR, 4)
conv_stream_kernel(const float* __restrict__ x, const float* __restrict__ wt,
                   const float* __restrict__ gamma, const float* __restrict__ beta,
                   float* __restrict__ out)
{
    extern __shared__ float4 smem4[];
    const int hc = blockIdx.x;
    const int bc = blockIdx.y;
    const int c  = bc & (CCH - 1);
    const int h0 = hc * CH_ROWS;
    const int tid  = threadIdx.x;
    const int lane = tid & 31;
    const int olb  = (tid >> 5) * 4;               // warp's 4 output rows within the chunk
    const float* xs = x + (size_t)bc * SLAB;

    u64 W2p[9], W1p[9], W0p[9];
    #pragma unroll
    for (int i = 0; i < 9; ++i) {
        float w0 = __ldg(wt + c * 27 + 0 * 9 + i);
        float w1 = __ldg(wt + c * 27 + 1 * 9 + i);
        float w2 = __ldg(wt + c * 27 + 2 * 9 + i);
        W0p[i] = pk2(w0, w0);
        W1p[i] = pk2(w1, w1);
        W2p[i] = pk2(w2, w2);
    }

    u64 gsc2 = 0, bsc2 = 0;
    float* outp = out + (size_t)bc * SLAB + (size_t)(h0 + olb) * WW + lane * 4;
    if (PASS == 2) {
        const float rstd = g_rstd[bc], mean = g_mean[bc];
        const float gsc = gamma[c] * rstd;
        const float bsc = fmaf(-mean, gsc, beta[c]);
        gsc2 = pk2(gsc, gsc);
        bsc2 = pk2(bsc, bsc);
    }

    // prologue: planes 0,1 in flight (slots 0,1) as one group
    load_plane(xs, 0, h0, smem4,            tid);
    load_plane(xs, 1, h0, smem4 + PLANE_F4, tid);
    commit_g();

    u64 A[8], B[8], C[8];          // never pre-initialized: fresh banks start with mul
    u64 s2 = 0ull, q2 = 0ull;

    // S_0: z=0,1 (slots 0,1). N=A(out0) fresh, F=B(out1); second conv retires out0,
    // leaves B=out1(w0,w1), C=out2(w0). Chain: next call gets (B, C, A).
    sstep<PASS, 0, 1, true, false>(0, xs, smem4, h0, tid, olb, lane,
                                   W2p, W1p, W0p, C, A, B, s2, q2, gsc2, bsc2, outp);

    // S_1..S_30: 5 blocks of 6 supersteps (slot parity x 3-cycle of bank roles)
    for (int b = 0; b < 5; ++b) {
        const int z0 = 12 * b;
        sstep<PASS, 2, 3, false, false>(z0 + 2,  xs, smem4, h0, tid, olb, lane,
                                        W2p, W1p, W0p, B, C, A, s2, q2, gsc2, bsc2, outp);
        sstep<PASS, 0, 1, false, false>(z0 + 4,  xs, smem4, h0, tid, olb, lane,
                                        W2p, W1p, W0p, A, B, C, s2, q2, gsc2, bsc2, outp);
        sstep<PASS, 2, 3, false, false>(z0 + 6,  xs, smem4, h0, tid, olb, lane,
                                        W2p, W1p, W0p, C, A, B, s2, q2, gsc2, bsc2, outp);
        sstep<PASS, 0, 1, false, false>(z0 + 8,  xs, smem4, h0, tid, olb, lane,
                                        W2p, W1p, W0p, B, C, A, s2, q2, gsc2, bsc2, outp);
        sstep<PASS, 2, 3, false, false>(z0 + 10, xs, smem4, h0, tid, olb, lane,
                                        W2p, W1p, W0p, A, B, C, s2, q2, gsc2, bsc2, outp);
        sstep<PASS, 0, 1, false, false>(z0 + 12, xs, smem4, h0, tid, olb, lane,
                                        W2p, W1p, W0p, C, A, B, s2, q2, gsc2, bsc2, outp);
    }

    // S_31: z=62,63 (slots 2,3); no prefetch; retires out61, out62, out63
    sstep<PASS, 2, 3, false, true>(62, xs, smem4, h0, tid, olb, lane,
                                   W2p, W1p, W0p, B, C, A, s2, q2, gsc2, bsc2, outp);

    if (PASS == 1) {
        float sl, sh, ql, qh;
        upk2(s2, sl, sh); upk2(q2, ql, qh);
        float s = sl + sh, q = ql + qh;
        #pragma unroll
        for (int off = 16; off > 0; off >>= 1) {
            s += __shfl_down_sync(0xffffffffu, s, off);
            q += __shfl_down_sync(0xffffffffu, q, off);
        }
        __syncthreads();                 // compute done; smem reusable
        float* red = (float*)smem4;
        const int warp = tid >> 5;
        if (lane == 0) { red[warp] = s; red[8 + warp] = q; }
        __syncthreads();
        if (tid == 0) {
            g_psum[bc * NCHUNK + hc] = red[0] + red[1] + red[2] + red[3];
            g_psq [bc * NCHUNK + hc] = red[8] + red[9] + red[10] + red[11];
        }
    }
}

__global__ void finalize_stats_kernel()
{
    const int bc = threadIdx.x;
    if (bc >= BC) return;
    double s = 0.0, q = 0.0;
    #pragma unroll
    for (int j = 0; j < NCHUNK; ++j) {
        s += (double)g_psum[bc * NCHUNK + j];
        q += (double)g_psq [bc * NCHUNK + j];
    }
    const double n = (double)SLAB;
    const double mean = s / n;
    const double var  = q / n - mean * mean;
    g_mean[bc] = (float)mean;
    g_rstd[bc] = (float)(1.0 / sqrt(var + 1e-5));
}

extern "C" void kernel_launch(void* const* d_in, const int* in_sizes, int n_in,
                              void* d_out, int out_size)
{
    (void)in_sizes; (void)n_in; (void)out_size;
    const float* x     = (const float*)d_in[0];
    const float* w     = (const float*)d_in[1];
    const float* gamma = (const float*)d_in[2];
    const float* beta  = (const float*)d_in[3];
    float* out = (float*)d_out;

    dim3 grid(NCHUNK, BC);  // 1024 CTAs of 128 threads; 4 CTAs/SM (smem 147KB/SM)
    conv_stream_kernel<1><<<grid, NTHR, SMEM_BYTES>>>(x, w, gamma, beta, out);
    finalize_stats_kernel<<<1, BC>>>();
    conv_stream_kernel<2><<<grid, NTHR, SMEM_BYTES>>>(x, w, gamma, beta, out);
}

// round 16
// speedup vs baseline: 1.4146x; 1.4146x over previous
#include <cuda_runtime.h>
#include <math.h>

#define DD    64
#define HH    128
#define WW    128
#define HW    (HH * WW)            // 16384
#define BC    128
#define CCH   64
#define SLAB  ((size_t)DD * HW)    // 1,048,576 per (b,c)
#define NTHR  128                  // 4 warps; warp = 4 output rows x full W
#define NCHUNK 8                   // H split into 8 chunks of 16 rows
#define CH_ROWS 16
#define LROWS 18                   // 16 output rows + 2 halo rows
#define ROW_F4 (WW / 4)            // 32 float4 per row
#define PLANE_F4 (LROWS * ROW_F4)  // 576 float4 per tile-plane
#define SMEM_BYTES (3 * PLANE_F4 * 16)  // 27648 B (3-slot ring)

typedef unsigned long long u64;

__device__ float g_psum[BC * NCHUNK];
__device__ float g_psq [BC * NCHUNK];
__device__ float g_mean[BC];
__device__ float g_rstd[BC];

// ---- packed fp32x2 helpers ----
__device__ __forceinline__ u64 pk2(float lo, float hi) {
    u64 r;
    asm("mov.b64 %0, {%1, %2};" : "=l"(r)
        : "r"(__float_as_uint(lo)), "r"(__float_as_uint(hi)));
    return r;
}
__device__ __forceinline__ void upk2(u64 v, float& lo, float& hi) {
    unsigned int a, b;
    asm("mov.b64 {%0, %1}, %2;" : "=r"(a), "=r"(b) : "l"(v));
    lo = __uint_as_float(a); hi = __uint_as_float(b);
}
__device__ __forceinline__ void fma2i(u64& acc, u64 a, u64 b) {
    asm("fma.rn.f32x2 %0, %1, %2, %0;" : "+l"(acc) : "l"(a), "l"(b));
}
__device__ __forceinline__ u64 fma2o(u64 a, u64 b, u64 c) {
    u64 d;
    asm("fma.rn.f32x2 %0, %1, %2, %3;" : "=l"(d) : "l"(a), "l"(b), "l"(c));
    return d;
}
__device__ __forceinline__ u64 mul2(u64 a, u64 b) {
    u64 d;
    asm("mul.rn.f32x2 %0, %1, %2;" : "=l"(d) : "l"(a), "l"(b));
    return d;
}
__device__ __forceinline__ void add2i(u64& acc, u64 a) {
    asm("add.rn.f32x2 %0, %1, %0;" : "+l"(acc) : "l"(a));
}
__device__ __forceinline__ void commit_g() {
    asm volatile("cp.async.commit_group;" ::: "memory");
}

// ---- async tile-plane load: 18 rows x 128 cols, zero-filled at H edges ----
__device__ __forceinline__ void load_plane(const float* __restrict__ xs, int z, int h0,
                                           float4* __restrict__ buf, int tid)
{
    const float* src = xs + (size_t)z * HW;
    unsigned int sbase = (unsigned int)__cvta_generic_to_shared(buf);
    #pragma unroll
    for (int it = 0; it < 5; ++it) {                 // 576 f4 / 128 thr = 4.5
        int i = tid + it * NTHR;
        if (it < 4 || i < PLANE_F4) {
            int row = i >> 5;
            int c4  = i & 31;
            int h   = h0 - 1 + row;
            if ((unsigned)h < (unsigned)HH) {
                const float* g = src + h * WW + c4 * 4;
                unsigned int sa = sbase + i * 16;
                asm volatile("cp.async.cg.shared.global [%0], [%1], 16;"
                             :: "r"(sa), "l"(g));
            } else {
                buf[i] = make_float4(0.f, 0.f, 0.f, 0.f);  // H zero-pad
            }
        }
    }
}

// ---- ONE sweep over the warp's 6 smem rows feeding up to THREE targets ----
// O += W(dz=2)*plane (completes out[z-1]); N += W(dz=1)*plane; F = W(dz=0)*plane.
// F is "fresh": first tap per accumulator is mul (no zero-init anywhere).
// NFRESH: N is also fresh (only for the very first plane, z = 0).
template<bool HO, bool HF, bool NFRESH>
__device__ __forceinline__ void conv3(const float4* __restrict__ buf, int olb, int lane,
    const u64 (&W2p)[9], const u64 (&W1p)[9], const u64 (&W0p)[9],
    u64 (&O)[8], u64 (&N)[8], u64 (&F)[8])
{
    #pragma unroll
    for (int r = 0; r < 6; ++r) {
        float4 q = buf[(olb + r) * ROW_F4 + lane];
        float left  = __shfl_up_sync(0xffffffffu, q.w, 1);
        float right = __shfl_down_sync(0xffffffffu, q.x, 1);
        if (lane == 0)  left  = 0.f;   // true W zero-pad
        if (lane == 31) right = 0.f;
        u64 pp0 = pk2(left, q.x);
        u64 pp1 = pk2(q.x,  q.y);
        u64 pp2 = pk2(q.y,  q.z);
        u64 pp3 = pk2(q.z,  q.w);
        u64 pp4 = pk2(q.w,  right);
        #pragma unroll
        for (int oo = 0; oo < 4; ++oo) {
            const int dy = r - oo;                   // tap index; folds at compile time
            if (dy < 0 || dy > 2) continue;
            if (HO) {
                const u64 w0 = W2p[dy * 3 + 0], w1 = W2p[dy * 3 + 1], w2 = W2p[dy * 3 + 2];
                fma2i(O[2 * oo + 0], pp0, w0);
                fma2i(O[2 * oo + 0], pp1, w1);
                fma2i(O[2 * oo + 0], pp2, w2);
                fma2i(O[2 * oo + 1], pp2, w0);
                fma2i(O[2 * oo + 1], pp3, w1);
                fma2i(O[2 * oo + 1], pp4, w2);
            }
            {
                const u64 w0 = W1p[dy * 3 + 0], w1 = W1p[dy * 3 + 1], w2 = W1p[dy * 3 + 2];
                if (NFRESH && dy == 0) {             // first-ever touch of this output
                    N[2 * oo + 0] = mul2(pp0, w0);
                    N[2 * oo + 1] = mul2(pp2, w0);
                } else {
                    fma2i(N[2 * oo + 0], pp0, w0);
                    fma2i(N[2 * oo + 1], pp2, w0);
                }
                fma2i(N[2 * oo + 0], pp1, w1);
                fma2i(N[2 * oo + 0], pp2, w2);
                fma2i(N[2 * oo + 1], pp3, w1);
                fma2i(N[2 * oo + 1], pp4, w2);
            }
            if (HF) {
                const u64 w0 = W0p[dy * 3 + 0], w1 = W0p[dy * 3 + 1], w2 = W0p[dy * 3 + 2];
                if (dy == 0) {                       // F bank fresh: overwrite, no init
                    F[2 * oo + 0] = mul2(pp0, w0);
                    F[2 * oo + 1] = mul2(pp2, w0);
                } else {
                    fma2i(F[2 * oo + 0], pp0, w0);
                    fma2i(F[2 * oo + 1], pp2, w0);
                }
                fma2i(F[2 * oo + 0], pp1, w1);
                fma2i(F[2 * oo + 0], pp2, w2);
                fma2i(F[2 * oo + 1], pp3, w1);
                fma2i(F[2 * oo + 1], pp4, w2);
            }
        }
    }
}

// ---- finalize a completed output plane: stats (pass1) or normalize+relu+store (pass2) ----
template<int PASS>
__device__ __forceinline__ void finalize(u64 (&A)[8], int d, u64& s2, u64& q2,
                                         u64 gsc2, u64 bsc2, float* __restrict__ outp)
{
    if (PASS == 1) {
        #pragma unroll
        for (int i = 0; i < 8; ++i) { add2i(s2, A[i]); fma2i(q2, A[i], A[i]); }
    } else {
        float* os = outp + (size_t)d * HW;
        #pragma unroll
        for (int oo = 0; oo < 4; ++oo) {
            u64 ya = fma2o(A[2 * oo + 0], gsc2, bsc2);
            u64 yb = fma2o(A[2 * oo + 1], gsc2, bsc2);
            float a0, a1, a2, a3;
            upk2(ya, a0, a1); upk2(yb, a2, a3);
            float4 r4;
            r4.x = fmaxf(a0, 0.f); r4.y = fmaxf(a1, 0.f);
            r4.z = fmaxf(a2, 0.f); r4.w = fmaxf(a3, 0.f);
            *(float4*)(os + oo * WW) = r4;
        }
    }
}

// ---- one z-step, slots compile-time. R13-proven flow: wait plane z (1 outstanding),
// barrier (protects slot PSLOT = plane z-1's slot), prefetch z+2 into PSLOT, sweep, retire.
// Fresh F via mul in conv3 -> NO bank zeroing after finalize.
template<int PASS, int SLOT, int PSLOT>
__device__ __forceinline__ void step3(int z, const float* __restrict__ xs,
        float4* __restrict__ smem4, int h0, int tid, int olb, int lane,
        const u64 (&W2p)[9], const u64 (&W1p)[9], const u64 (&W0p)[9],
        u64 (&O)[8], u64 (&N)[8], u64 (&F)[8],
        u64& s2, u64& q2, u64 gsc2, u64 bsc2, float* __restrict__ outp)
{
    asm volatile("cp.async.wait_group 1;" ::: "memory");  // plane z resident
    __syncthreads();                                      // all warps done with plane z-1
    const int zp = z + 2;
    if (zp < DD) load_plane(xs, zp, h0, smem4 + PSLOT * PLANE_F4, tid);
    commit_g();  // one group per step (possibly empty) keeps the count invariant
    conv3<true, true, false>(smem4 + SLOT * PLANE_F4, olb, lane, W2p, W1p, W0p, O, N, F);
    finalize<PASS>(O, z - 1, s2, q2, gsc2, bsc2, outp);
    // O is dead here; it becomes the next step's F and is freshly overwritten by mul.
}

// PASS 1: streaming conv + per-CTA (sum,sumsq).  PASS 2: conv + norm + relu + store.
template<int PASS>
__global__ void __launch_bounds__(NTHR, 4)
conv_stream_kernel(const float* __restrict__ x, const float* __restrict__ wt,
                   const float* __restrict__ gamma, const float* __restrict__ beta,
                   float* __restrict__ out)
{
    extern __shared__ float4 smem4[];
    const int hc = blockIdx.x;
    const int bc = blockIdx.y;
    const int c  = bc & (CCH - 1);
    const int h0 = hc * CH_ROWS;
    const int tid  = threadIdx.x;
    const int lane = tid & 31;
    const int olb  = (tid >> 5) * 4;               // warp's 4 output rows within the chunk
    const float* xs = x + (size_t)bc * SLAB;

    u64 W2p[9], W1p[9], W0p[9];
    #pragma unroll
    for (int i = 0; i < 9; ++i) {
        float w0 = __ldg(wt + c * 27 + 0 * 9 + i);
        float w1 = __ldg(wt + c * 27 + 1 * 9 + i);
        float w2 = __ldg(wt + c * 27 + 2 * 9 + i);
        W0p[i] = pk2(w0, w0);
        W1p[i] = pk2(w1, w1);
        W2p[i] = pk2(w2, w2);
    }

    u64 gsc2 = 0, bsc2 = 0;
    float* outp = out + (size_t)bc * SLAB + (size_t)(h0 + olb) * WW + lane * 4;
    if (PASS == 2) {
        const float rstd = g_rstd[bc], mean = g_mean[bc];
        const float gsc = gamma[c] * rstd;
        const float bsc = fmaf(-mean, gsc, beta[c]);
        gsc2 = pk2(gsc, gsc);
        bsc2 = pk2(bsc, bsc);
    }

    // prologue: planes 0,1 in flight (slots 0,1)
    load_plane(xs, 0, h0, smem4,            tid); commit_g();
    load_plane(xs, 1, h0, smem4 + PLANE_F4, tid); commit_g();

    u64 A0[8], A1[8], A2[8];       // never zero-initialized: fresh banks start with mul
    u64 s2 = 0ull, q2 = 0ull;

    // z = 0 (slot 0; plane -1 zero -> no O): N=A0 (out[0], fresh), F=A1 (out[1], fresh)
    asm volatile("cp.async.wait_group 1;" ::: "memory");
    __syncthreads();
    load_plane(xs, 2, h0, smem4 + 2 * PLANE_F4, tid); commit_g();
    conv3<false, true, true>(smem4, olb, lane, W2p, W1p, W0p, A2, A0, A1);

    // z = 1..60: slot = z%3, bank roles rotate with the same period-3 -> all compile-time
    for (int t = 0; t < 20; ++t) {
        const int z = 3 * t;
        step3<PASS, 1, 0>(z + 1, xs, smem4, h0, tid, olb, lane, W2p, W1p, W0p,
                          A0, A1, A2, s2, q2, gsc2, bsc2, outp);
        step3<PASS, 2, 1>(z + 2, xs, smem4, h0, tid, olb, lane, W2p, W1p, W0p,
                          A1, A2, A0, s2, q2, gsc2, bsc2, outp);
        step3<PASS, 0, 2>(z + 3, xs, smem4, h0, tid, olb, lane, W2p, W1p, W0p,
                          A2, A0, A1, s2, q2, gsc2, bsc2, outp);
    }
    step3<PASS, 1, 0>(61, xs, smem4, h0, tid, olb, lane, W2p, W1p, W0p,
                      A0, A1, A2, s2, q2, gsc2, bsc2, outp);
    step3<PASS, 2, 1>(62, xs, smem4, h0, tid, olb, lane, W2p, W1p, W0p,
                      A1, A2, A0, s2, q2, gsc2, bsc2, outp);

    // z = 63 (slot 0; plane 64 zero -> no F): O=A2 (out[62]), N=A0 (out[63])
    asm volatile("cp.async.wait_group 0;" ::: "memory");
    __syncthreads();
    conv3<true, false, false>(smem4, olb, lane, W2p, W1p, W0p, A2, A0, A1);
    finalize<PASS>(A2, 62, s2, q2, gsc2, bsc2, outp);
    finalize<PASS>(A0, 63, s2, q2, gsc2, bsc2, outp);

    if (PASS == 1) {
        float sl, sh, ql, qh;
        upk2(s2, sl, sh); upk2(q2, ql, qh);
        float s = sl + sh, q = ql + qh;
        #pragma unroll
        for (int off = 16; off > 0; off >>= 1) {
            s += __shfl_down_sync(0xffffffffu, s, off);
            q += __shfl_down_sync(0xffffffffu, q, off);
        }
        __syncthreads();                 // compute done; smem reusable
        float* red = (float*)smem4;
        const int warp = tid >> 5;
        if (lane == 0) { red[warp] = s; red[8 + warp] = q; }
        __syncthreads();
        if (tid == 0) {
            g_psum[bc * NCHUNK + hc] = red[0] + red[1] + red[2] + red[3];
            g_psq [bc * NCHUNK + hc] = red[8] + red[9] + red[10] + red[11];
        }
    }
}

__global__ void finalize_stats_kernel()
{
    const int bc = threadIdx.x;
    if (bc >= BC) return;
    double s = 0.0, q = 0.0;
    #pragma unroll
    for (int j = 0; j < NCHUNK; ++j) {
        s += (double)g_psum[bc * NCHUNK + j];
        q += (double)g_psq [bc * NCHUNK + j];
    }
    const double n = (double)SLAB;
    const double mean = s / n;
    const double var  = q / n - mean * mean;
    g_mean[bc] = (float)mean;
    g_rstd[bc] = (float)(1.0 / sqrt(var + 1e-5));
}

extern "C" void kernel_launch(void* const* d_in, const int* in_sizes, int n_in,
                              void* d_out, int out_size)
{
    (void)in_sizes; (void)n_in; (void)out_size;
    const float* x     = (const float*)d_in[0];
    const float* w     = (const float*)d_in[1];
    const float* gamma = (const float*)d_in[2];
    const float* beta  = (const float*)d_in[3];
    float* out = (float*)d_out;

    dim3 grid(NCHUNK, BC);  // 1024 CTAs of 128 threads; 4 CTAs/SM (smem 110KB, regs<=128)
    conv_stream_kernel<1><<<grid, NTHR, SMEM_BYTES>>>(x, w, gamma, beta, out);
    finalize_stats_kernel<<<1, BC>>>();
    conv_stream_kernel<2><<<grid, NTHR, SMEM_BYTES>>>(x, w, gamma, beta, out);
}